// round 2
// baseline (speedup 1.0000x reference)
#include <cuda_runtime.h>
#include <cstdint>

#define NN 100000
#define NE 1000000
#define HID 64

// ---------------- device scratch (static globals; no allocation allowed) ----
__device__ float g_P[(size_t)NN * HID];     // projected features h@W1
__device__ float g_agg[(size_t)NN * HID];   // scatter-add accumulator
__device__ float g_xs[3][(size_t)NN * HID]; // per-layer outputs (for concat)
__device__ int   g_is64;                    // edge_index dtype flag

// ---------------- dtype detection (int64 vs int32 edge_index) ---------------
__global__ void detect_k(const int* __restrict__ ei) {
    if (threadIdx.x == 0 && blockIdx.x == 0) {
        int is64 = 1;
        for (int e = 0; e < 64; e++) {
            if (ei[2 * e + 1] != 0) { is64 = 0; break; }  // high words of int64 src are 0
        }
        g_is64 = is64;
    }
}

// ---------------- zero the aggregation buffer -------------------------------
__global__ void zero_k(float4* __restrict__ p, int n4) {
    int i = blockIdx.x * 256 + threadIdx.x;
    if (i < n4) p[i] = make_float4(0.f, 0.f, 0.f, 0.f);
}

// ---------------- edge scatter-add: agg[dst] += w * P[src] (64 ch) ----------
// one thread handles (edge, 4 channels); 16 threads per edge
__global__ __launch_bounds__(256) void edge_k(const int* __restrict__ ei,
                                              const float* __restrict__ ew,
                                              const float* __restrict__ P,
                                              float* __restrict__ agg) {
    int t = blockIdx.x * 256 + threadIdx.x;   // < 16M, fits int
    int e = t >> 4;
    int g = (t & 15) * 4;
    int src, dst;
    if (g_is64) {
        const long long* e64 = (const long long*)ei;
        src = (int)e64[e];
        dst = (int)e64[NE + e];
    } else {
        src = ei[e];
        dst = ei[NE + e];
    }
    float w = ew[e];
    float4 v = *(const float4*)(P + (size_t)src * HID + g);
    float* p = agg + (size_t)dst * HID + g;
    asm volatile("red.global.add.v4.f32 [%0], {%1, %2, %3, %4};"
                 :: "l"(p), "f"(v.x * w), "f"(v.y * w), "f"(v.z * w), "f"(v.w * w)
                 : "memory");
}

// ---------------- fused GEMM kernel -----------------------------------------
// MODE 0: Out[N,NOUT] = A0[N,K] @ B[K,NOUT]                       (projection)
// MODE 1: A = relu(bn((1+eps)*P + agg + b1)); Out = relu(A@B + b2) (MLP tail)
// MODE 2: A = concat(A0,A1,A2); Out = A@B + bias2                  (final)
template <int K, int NOUT, int MODE>
__global__ __launch_bounds__(256) void gemm_k(
    const float* __restrict__ A0, const float* __restrict__ A1,
    const float* __restrict__ A2, const float* __restrict__ B,
    const float* __restrict__ b1, const float* __restrict__ gam,
    const float* __restrict__ bet, const float* __restrict__ mean,
    const float* __restrict__ var, const float* __restrict__ epsp,
    const float* __restrict__ bias2, float* __restrict__ Out) {
    constexpr int BM = 64;
    constexpr int KP = K + 1;          // pad to kill LDS bank conflicts
    constexpr int CG = NOUT / 4;       // column groups (float4 per thread)
    constexpr int RPT = (BM * CG) / 256;  // rows per thread

    extern __shared__ float sm[];
    float* As = sm;                  // BM * KP
    float* Bs = As + BM * KP;        // K * NOUT
    float* sc = Bs + K * NOUT;       // 64 (MODE 1)
    float* sh = sc + 64;             // 64 (MODE 1)

    int tid = threadIdx.x;
    int m0 = blockIdx.x * BM;

    if constexpr (MODE == 1) {
        if (tid < 64) {
            float s = gam[tid] * rsqrtf(var[tid] + 1e-5f);
            sc[tid] = s;
            sh[tid] = (b1[tid] - mean[tid]) * s + bet[tid];
        }
        __syncthreads();
    }

    float ev = 0.f;
    if constexpr (MODE == 1) ev = 1.0f + epsp[0];

    // ---- stage A tile (with fused pointwise transform for MODE 1/2) ----
    for (int i = tid; i < BM * (K / 4); i += 256) {
        int r = i / (K / 4), c4 = i % (K / 4);
        int m = m0 + r;
        float o0 = 0.f, o1 = 0.f, o2 = 0.f, o3 = 0.f;
        if (m < NN) {
            if constexpr (MODE == 0) {
                float4 v = *(const float4*)(A0 + (size_t)m * K + c4 * 4);
                o0 = v.x; o1 = v.y; o2 = v.z; o3 = v.w;
            } else if constexpr (MODE == 1) {
                float4 p = *(const float4*)(A0 + (size_t)m * HID + c4 * 4);
                float4 a = *(const float4*)(A1 + (size_t)m * HID + c4 * 4);
                int ch = c4 * 4;
                o0 = fmaxf(fmaf(fmaf(ev, p.x, a.x), sc[ch + 0], sh[ch + 0]), 0.f);
                o1 = fmaxf(fmaf(fmaf(ev, p.y, a.y), sc[ch + 1], sh[ch + 1]), 0.f);
                o2 = fmaxf(fmaf(fmaf(ev, p.z, a.z), sc[ch + 2], sh[ch + 2]), 0.f);
                o3 = fmaxf(fmaf(fmaf(ev, p.w, a.w), sc[ch + 3], sh[ch + 3]), 0.f);
            } else {
                int ch = c4 * 4;
                const float* src = (ch < 64) ? A0 : (ch < 128 ? A1 : A2);
                int cc = ch & 63;
                float4 v = *(const float4*)(src + (size_t)m * HID + cc);
                o0 = v.x; o1 = v.y; o2 = v.z; o3 = v.w;
            }
        }
        float* dst = As + r * KP + c4 * 4;
        dst[0] = o0; dst[1] = o1; dst[2] = o2; dst[3] = o3;
    }
    // ---- stage B tile ----
    for (int i = tid; i < K * NOUT / 4; i += 256)
        ((float4*)Bs)[i] = ((const float4*)B)[i];
    __syncthreads();

    int tx = tid % CG, ty = tid / CG;
    float acc[RPT][4];
#pragma unroll
    for (int i = 0; i < RPT; i++)
        acc[i][0] = acc[i][1] = acc[i][2] = acc[i][3] = 0.f;

    const float4* B4 = (const float4*)Bs;
#pragma unroll 8
    for (int k = 0; k < K; k++) {
        float4 b = B4[k * CG + tx];
#pragma unroll
        for (int i = 0; i < RPT; i++) {
            float a = As[(ty * RPT + i) * KP + k];
            acc[i][0] = fmaf(a, b.x, acc[i][0]);
            acc[i][1] = fmaf(a, b.y, acc[i][1]);
            acc[i][2] = fmaf(a, b.z, acc[i][2]);
            acc[i][3] = fmaf(a, b.w, acc[i][3]);
        }
    }

    float4 bb = make_float4(0.f, 0.f, 0.f, 0.f);
    if constexpr (MODE != 0) bb = *(const float4*)(bias2 + tx * 4);

#pragma unroll
    for (int i = 0; i < RPT; i++) {
        int m = m0 + ty * RPT + i;
        if (m < NN) {
            float4 o;
            o.x = acc[i][0] + bb.x;
            o.y = acc[i][1] + bb.y;
            o.z = acc[i][2] + bb.z;
            o.w = acc[i][3] + bb.w;
            if constexpr (MODE == 1) {
                o.x = fmaxf(o.x, 0.f); o.y = fmaxf(o.y, 0.f);
                o.z = fmaxf(o.z, 0.f); o.w = fmaxf(o.w, 0.f);
            }
            *(float4*)(Out + (size_t)m * NOUT + tx * 4) = o;
        }
    }
}

// ---------------- host launcher ---------------------------------------------
extern "C" void kernel_launch(void* const* d_in, const int* in_sizes, int n_in,
                              void* d_out, int out_size) {
    const float* x    = (const float*)d_in[0];
    const int*   ei   = (const int*)d_in[1];
    const float* ew   = (const float*)d_in[2];
    const float* eps  = (const float*)d_in[3];
    const float* W1_0 = (const float*)d_in[4];
    const float* b1_0 = (const float*)d_in[5];
    const float* W1_r = (const float*)d_in[6];
    const float* b1_r = (const float*)d_in[7];
    const float* W2   = (const float*)d_in[8];
    const float* b2   = (const float*)d_in[9];
    const float* gam  = (const float*)d_in[10];
    const float* bet  = (const float*)d_in[11];
    const float* mean = (const float*)d_in[12];
    const float* var  = (const float*)d_in[13];
    const float* l2W  = (const float*)d_in[14];
    const float* l2b  = (const float*)d_in[15];
    float* out = (float*)d_out;

    float *P, *AGG, *XS;
    cudaGetSymbolAddress((void**)&P, g_P);
    cudaGetSymbolAddress((void**)&AGG, g_agg);
    cudaGetSymbolAddress((void**)&XS, g_xs);
    float* xs0 = XS;
    float* xs1 = XS + (size_t)NN * HID;
    float* xs2 = XS + 2 * (size_t)NN * HID;

    // dynamic shared sizes: (BM*(K+1) + K*NOUT + 128) * 4
    const int SM_128_64 = (64 * 129 + 128 * 64 + 128) * 4;  // 66304
    const int SM_64_64  = (64 * 65 + 64 * 64 + 128) * 4;    // 33536
    const int SM_192_32 = (64 * 193 + 192 * 32 + 128) * 4;  // 74496

    cudaFuncSetAttribute(gemm_k<128, 64, 0>,
                         cudaFuncAttributeMaxDynamicSharedMemorySize, SM_128_64);
    cudaFuncSetAttribute(gemm_k<192, 32, 2>,
                         cudaFuncAttributeMaxDynamicSharedMemorySize, SM_192_32);

    const int GB = (NN + 63) / 64;          // 1563 blocks
    const int ZB = (NN * HID / 4 + 255) / 256;  // zero-kernel blocks
    const int EB = (NE * 16) / 256;         // 62500 edge blocks

    detect_k<<<1, 1>>>(ei);

    // ----- layer 0 -----
    gemm_k<128, 64, 0><<<GB, 256, SM_128_64>>>(x, 0, 0, W1_0,
                                               0, 0, 0, 0, 0, 0, 0, P);
    zero_k<<<ZB, 256>>>((float4*)AGG, NN * HID / 4);
    edge_k<<<EB, 256>>>(ei, ew, P, AGG);
    gemm_k<64, 64, 1><<<GB, 256, SM_64_64>>>(P, AGG, 0, W2,
                                             b1_0, gam, bet, mean, var,
                                             eps, b2, xs0);
    // ----- layer 1 -----
    gemm_k<64, 64, 0><<<GB, 256, SM_64_64>>>(xs0, 0, 0, W1_r,
                                             0, 0, 0, 0, 0, 0, 0, P);
    zero_k<<<ZB, 256>>>((float4*)AGG, NN * HID / 4);
    edge_k<<<EB, 256>>>(ei, ew, P, AGG);
    gemm_k<64, 64, 1><<<GB, 256, SM_64_64>>>(P, AGG, 0, W2 + 4096,
                                             b1_r, gam + 64, bet + 64,
                                             mean + 64, var + 64,
                                             eps + 1, b2 + 64, xs1);
    // ----- layer 2 -----
    gemm_k<64, 64, 0><<<GB, 256, SM_64_64>>>(xs1, 0, 0, W1_r + 4096,
                                             0, 0, 0, 0, 0, 0, 0, P);
    zero_k<<<ZB, 256>>>((float4*)AGG, NN * HID / 4);
    edge_k<<<EB, 256>>>(ei, ew, P, AGG);
    gemm_k<64, 64, 1><<<GB, 256, SM_64_64>>>(P, AGG, 0, W2 + 8192,
                                             b1_r + 64, gam + 128, bet + 128,
                                             mean + 128, var + 128,
                                             eps + 2, b2 + 128, xs2);
    // ----- final projection (concat fused) -----
    gemm_k<192, 32, 2><<<GB, 256, SM_192_32>>>(xs0, xs1, xs2, l2W,
                                               0, 0, 0, 0, 0, 0, l2b, out);
}